// round 8
// baseline (speedup 1.0000x reference)
#include <cuda_runtime.h>
#include <cuda_bf16.h>

// SoftPool2d: 3x3 window, stride 2, pad 1; zero-padding participates in softmax.
// x: [16,96,224,224] f32 -> out: [16,96,112,112] f32.
// Each thread computes a 2x4 output tile (2 rows x 4 cols) from a 5x9 input
// patch. Per row: 2 aligned LDG.128 (cols 8P..8P+7); the left-halo col 8P-1
// comes from lane-1's C.w via __shfl_up_sync. Warp-edge repair: lane 0 with
// P!=0 cannot shuffle across the warp boundary, so that single lane does a
// predicated scalar LDG of col 8P-1 (1-lane wavefront, ~zero cost).
// alpha folded in per-thread: alpha*log2e = log2(1 + 2^(raw*log2e)).

#define H_IN    224
#define W_IN    224
#define H_OUT   112
#define W_OUT   112
#define PLANE_IN  (H_IN * W_IN)     // 50176
#define PLANE_OUT (H_OUT * W_OUT)   // 12544
#define PT        28                 // col quads per plane (112/4)
#define QT        56                 // row pairs per plane (112/2)
#define TILES_PER_PLANE (PT * QT)    // 1568
#define N_PLANES  (16 * 96)          // 1536
#define TOTAL_TILES (TILES_PER_PLANE * N_PLANES)  // 2,408,448 = 9408 * 256 exactly

__device__ __forceinline__ float ex2f(float x) {
    float r;
    asm("ex2.approx.ftz.f32 %0, %1;" : "=f"(r) : "f"(x));
    return r;
}

__device__ __forceinline__ float lg2f(float x) {
    float r;
    asm("lg2.approx.ftz.f32 %0, %1;" : "=f"(r) : "f"(x));
    return r;
}

__device__ __forceinline__ float frcp(float x) {
    float r;
    asm("rcp.approx.ftz.f32 %0, %1;" : "=f"(r) : "f"(x));
    return r;
}

__global__ __launch_bounds__(256)
void softpool_kernel(const float* __restrict__ x,
                     const float* __restrict__ raw_alpha,
                     float* __restrict__ out) {
    unsigned idx = blockIdx.x * 256u + threadIdx.x;   // grid sized exactly

    // c = alpha * log2(e) = log2(1 + exp(raw_alpha))
    const float c = lg2f(1.0f + ex2f(__ldg(raw_alpha) * 1.44269504088896340736f));

    unsigned P  = idx % PT;          // output cols 4P..4P+3
    unsigned t  = idx / PT;
    unsigned q  = t % QT;            // output rows 2q, 2q+1
    unsigned nc = t / QT;

    const float* plane = x + (size_t)nc * PLANE_IN;

    // Input patch: rows 4q-1..4q+3, cols 8P-1..8P+7. Max index 223 -> only
    // top/left ever pad (8*27+7 = 223, 4*55+3 = 223).
    int row0 = 4 * (int)q - 1;
    int colB = 8 * (int)P;           // 16B-aligned
    bool left = (P == 0);
    bool top  = (q == 0);
    // Lane 0 cannot receive from the previous warp; repair with a scalar load.
    bool fixlane = ((threadIdx.x & 31u) == 0u) && !left;

    float n00 = 0.f, n01 = 0.f, n02 = 0.f, n03 = 0.f;
    float n10 = 0.f, n11 = 0.f, n12 = 0.f, n13 = 0.f;
    float d00 = 0.f, d01 = 0.f, d02 = 0.f, d03 = 0.f;
    float d10 = 0.f, d11 = 0.f, d12 = 0.f, d13 = 0.f;

#pragma unroll
    for (int r = 0; r < 5; ++r) {
        int rr = row0 + r;
        int rc = rr < 0 ? 0 : rr;          // clamp addr; values zeroed below
        const float* rp = plane + (size_t)rc * W_IN;

        float4 B = *(const float4*)(rp + colB);      // cols 8P..8P+3
        float4 C = *(const float4*)(rp + colB + 4);  // cols 8P+4..8P+7

        // Left halo col 8P-1: lane l>0 takes lane l-1's C.w (valid: contiguous
        // idx => same q,nc when P>=1; P==0 is the zero pad and masked by `left`).
        float h = __shfl_up_sync(0xFFFFFFFFu, C.w, 1);
        if (fixlane) h = __ldg(rp + colB - 1);       // single-lane predicated LDG
        float v0 = left ? 0.f : h;
        float v1 = B.x, v2 = B.y, v3 = B.z, v4 = B.w;
        float v5 = C.x, v6 = C.y, v7 = C.z, v8 = C.w;
        if (top && r == 0) {
            v0 = 0.f; v1 = 0.f; v2 = 0.f; v3 = 0.f; v4 = 0.f;
            v5 = 0.f; v6 = 0.f; v7 = 0.f; v8 = 0.f;
        }

        float e0 = ex2f(c * v0), e1 = ex2f(c * v1), e2 = ex2f(c * v2);
        float e3 = ex2f(c * v3), e4 = ex2f(c * v4), e5 = ex2f(c * v5);
        float e6 = ex2f(c * v6), e7 = ex2f(c * v7), e8 = ex2f(c * v8);

        // windows j=0..3 use taps {2j, 2j+1, 2j+2}; even taps shared
        float ve2 = v2 * e2, ve4 = v4 * e4, ve6 = v6 * e6;
        float dA = e0 + e1 + e2;
        float dB = e2 + e3 + e4;
        float dC = e4 + e5 + e6;
        float dD = e6 + e7 + e8;
        float nA = fmaf(v0, e0, fmaf(v1, e1, ve2));
        float nB = fmaf(v3, e3, ve2 + ve4);
        float nC = fmaf(v5, e5, ve4 + ve6);
        float nD = fmaf(v7, e7, fmaf(v8, e8, ve6));

        // rows 0..2 -> out row 2q; rows 2..4 -> out row 2q+1 (row 2 shared)
        if (r <= 2) {
            d00 += dA; d01 += dB; d02 += dC; d03 += dD;
            n00 += nA; n01 += nB; n02 += nC; n03 += nD;
        }
        if (r >= 2) {
            d10 += dA; d11 += dB; d12 += dC; d13 += dD;
            n10 += nA; n11 += nB; n12 += nC; n13 += nD;
        }
    }

    float* op = out + (size_t)nc * PLANE_OUT + (size_t)(2u * q) * W_OUT + 4u * P;
    *(float4*)op = make_float4(n00 * frcp(d00), n01 * frcp(d01),
                               n02 * frcp(d02), n03 * frcp(d03));
    *(float4*)(op + W_OUT) = make_float4(n10 * frcp(d10), n11 * frcp(d11),
                                         n12 * frcp(d12), n13 * frcp(d13));
}

extern "C" void kernel_launch(void* const* d_in, const int* in_sizes, int n_in,
                              void* d_out, int out_size) {
    const float* x         = (const float*)d_in[0];
    const float* raw_alpha = (const float*)d_in[1];
    float*       out       = (float*)d_out;

    const int block = 256;
    const int grid  = TOTAL_TILES / block;  // 9408, exact
    softpool_kernel<<<grid, block>>>(x, raw_alpha, out);
}

// round 9
// speedup vs baseline: 1.0070x; 1.0070x over previous
#include <cuda_runtime.h>
#include <cuda_bf16.h>

// SoftPool2d: 3x3 window, stride 2, pad 1; zero-padding participates in softmax.
// x: [16,96,224,224] f32 -> out: [16,96,112,112] f32.
// Champion shape (R4): each thread computes a 2x2 output tile from a 5x5 input
// patch via 10x LDG.128 (16B-aligned, NC path), 25 EX2, 2 STG.CS.64.
// Occupancy-first: 32 regs -> ~83% occ is what sustains DRAM >= 84%.
// alpha folded in per-thread: alpha*log2e = log2(1 + 2^(raw*log2e)).

#define H_IN    224
#define W_IN    224
#define H_OUT   112
#define W_OUT   112
#define PLANE_IN  (H_IN * W_IN)     // 50176
#define PLANE_OUT (H_OUT * W_OUT)   // 12544
#define PQ        56                 // output pairs per dim
#define TILES_PER_PLANE (PQ * PQ)    // 3136
#define N_PLANES  (16 * 96)          // 1536
#define TOTAL_TILES (TILES_PER_PLANE * N_PLANES)  // 4,816,896 = 18816 * 256 exactly

__device__ __forceinline__ float ex2f(float x) {
    float r;
    asm("ex2.approx.ftz.f32 %0, %1;" : "=f"(r) : "f"(x));
    return r;
}

__device__ __forceinline__ float lg2f(float x) {
    float r;
    asm("lg2.approx.ftz.f32 %0, %1;" : "=f"(r) : "f"(x));
    return r;
}

__device__ __forceinline__ float frcp(float x) {
    float r;
    asm("rcp.approx.ftz.f32 %0, %1;" : "=f"(r) : "f"(x));
    return r;
}

__global__ __launch_bounds__(256)
void softpool_kernel(const float* __restrict__ x,
                     const float* __restrict__ raw_alpha,
                     float* __restrict__ out) {
    unsigned idx = blockIdx.x * 256u + threadIdx.x;   // grid sized exactly

    // c = alpha * log2(e) = log2(1 + exp(raw_alpha))
    const float c = lg2f(1.0f + ex2f(__ldg(raw_alpha) * 1.44269504088896340736f));

    unsigned p  = idx % PQ;          // output col pair: cols 2p, 2p+1
    unsigned t  = idx / PQ;
    unsigned q  = t % PQ;            // output row pair: rows 2q, 2q+1
    unsigned nc = t / PQ;

    const float* plane = x + (size_t)nc * PLANE_IN;

    // Input patch: rows 4q-1..4q+3, cols 4p-1..4p+3.
    // Max index = 4*55+3 = 223 -> only top/left ever pad.
    int row0 = 4 * (int)q - 1;
    int colB = 4 * (int)p;                 // 16B-aligned float4 base (cols 4p..4p+3)
    int colA = colB >= 4 ? colB - 4 : 0;   // cols 4p-4..4p-1 (clamped for p=0, stays aligned)
    bool left = (p == 0);
    bool top  = (q == 0);

    float num00 = 0.f, num01 = 0.f, num10 = 0.f, num11 = 0.f;
    float den00 = 0.f, den01 = 0.f, den10 = 0.f, den11 = 0.f;

#pragma unroll
    for (int r = 0; r < 5; ++r) {
        int rr = row0 + r;
        int rc = rr < 0 ? 0 : rr;          // clamp addr; values zeroed below
        const float* rp = plane + (size_t)rc * W_IN;

        float4 A = __ldg((const float4*)(rp + colA));  // cols 4p-4..4p-1 (need .w)
        float4 B = __ldg((const float4*)(rp + colB));  // cols 4p..4p+3

        float v0 = left ? 0.f : A.w;
        float v1 = B.x, v2 = B.y, v3 = B.z, v4 = B.w;
        if (top && r == 0) { v0 = 0.f; v1 = 0.f; v2 = 0.f; v3 = 0.f; v4 = 0.f; }

        float e0 = ex2f(c * v0), e1 = ex2f(c * v1), e2 = ex2f(c * v2);
        float e3 = ex2f(c * v3), e4 = ex2f(c * v4);

        // left window = cols {0,1,2}, right window = cols {2,3,4}; col 2 shared
        float ve2 = v2 * e2;
        float dl = e0 + e1 + e2;
        float dr = e2 + e3 + e4;
        float nl = fmaf(v0, e0, fmaf(v1, e1, ve2));
        float nr = fmaf(v3, e3, fmaf(v4, e4, ve2));

        // rows 0..2 -> out row 2q; rows 2..4 -> out row 2q+1 (row 2 shared)
        if (r <= 2) { den00 += dl; den01 += dr; num00 += nl; num01 += nr; }
        if (r >= 2) { den10 += dl; den11 += dr; num10 += nl; num11 += nr; }
    }

    float* op = out + (size_t)nc * PLANE_OUT + (size_t)(2u * q) * W_OUT + 2u * p;
    // Streaming stores: output is write-once; keep it from displacing input rows in L2.
    __stcs((float2*)op,           make_float2(num00 * frcp(den00), num01 * frcp(den01)));
    __stcs((float2*)(op + W_OUT), make_float2(num10 * frcp(den10), num11 * frcp(den11)));
}

extern "C" void kernel_launch(void* const* d_in, const int* in_sizes, int n_in,
                              void* d_out, int out_size) {
    const float* x         = (const float*)d_in[0];
    const float* raw_alpha = (const float*)d_in[1];
    float*       out       = (float*)d_out;

    const int block = 256;
    const int grid  = TOTAL_TILES / block;  // 18816, exact
    softpool_kernel<<<grid, block>>>(x, raw_alpha, out);
}

// round 10
// speedup vs baseline: 1.0075x; 1.0005x over previous
#include <cuda_runtime.h>
#include <cuda_bf16.h>

// SoftPool2d: 3x3 window, stride 2, pad 1; zero-padding participates in softmax.
// x: [16,96,224,224] f32 -> out: [16,96,112,112] f32.
// Champion shape (R4): each thread computes a 2x2 output tile from a 5x5 input
// patch via 10x LDG.128 (16B-aligned, NC path), 25 EX2, 2 STG.CS.64.
// Occupancy-first: 32 regs -> ~83% occ is what sustains DRAM >= 84%.
// alpha folded in per-thread: alpha*log2e = log2(1 + 2^(raw*log2e)).

#define H_IN    224
#define W_IN    224
#define H_OUT   112
#define W_OUT   112
#define PLANE_IN  (H_IN * W_IN)     // 50176
#define PLANE_OUT (H_OUT * W_OUT)   // 12544
#define PQ        56                 // output pairs per dim
#define TILES_PER_PLANE (PQ * PQ)    // 3136
#define N_PLANES  (16 * 96)          // 1536
#define TOTAL_TILES (TILES_PER_PLANE * N_PLANES)  // 4,816,896 = 18816 * 256 exactly

__device__ __forceinline__ float ex2f(float x) {
    float r;
    asm("ex2.approx.ftz.f32 %0, %1;" : "=f"(r) : "f"(x));
    return r;
}

__device__ __forceinline__ float lg2f(float x) {
    float r;
    asm("lg2.approx.ftz.f32 %0, %1;" : "=f"(r) : "f"(x));
    return r;
}

__device__ __forceinline__ float frcp(float x) {
    float r;
    asm("rcp.approx.ftz.f32 %0, %1;" : "=f"(r) : "f"(x));
    return r;
}

__global__ __launch_bounds__(256)
void softpool_kernel(const float* __restrict__ x,
                     const float* __restrict__ raw_alpha,
                     float* __restrict__ out) {
    unsigned idx = blockIdx.x * 256u + threadIdx.x;   // grid sized exactly

    // c = alpha * log2(e) = log2(1 + exp(raw_alpha))
    const float c = lg2f(1.0f + ex2f(__ldg(raw_alpha) * 1.44269504088896340736f));

    unsigned p  = idx % PQ;          // output col pair: cols 2p, 2p+1
    unsigned t  = idx / PQ;
    unsigned q  = t % PQ;            // output row pair: rows 2q, 2q+1
    unsigned nc = t / PQ;

    const float* plane = x + (size_t)nc * PLANE_IN;

    // Input patch: rows 4q-1..4q+3, cols 4p-1..4p+3.
    // Max index = 4*55+3 = 223 -> only top/left ever pad.
    int row0 = 4 * (int)q - 1;
    int colB = 4 * (int)p;                 // 16B-aligned float4 base (cols 4p..4p+3)
    int colA = colB >= 4 ? colB - 4 : 0;   // cols 4p-4..4p-1 (clamped for p=0, stays aligned)
    bool left = (p == 0);
    bool top  = (q == 0);

    float num00 = 0.f, num01 = 0.f, num10 = 0.f, num11 = 0.f;
    float den00 = 0.f, den01 = 0.f, den10 = 0.f, den11 = 0.f;

#pragma unroll
    for (int r = 0; r < 5; ++r) {
        int rr = row0 + r;
        int rc = rr < 0 ? 0 : rr;          // clamp addr; values zeroed below
        const float* rp = plane + (size_t)rc * W_IN;

        float4 A = __ldg((const float4*)(rp + colA));  // cols 4p-4..4p-1 (need .w)
        float4 B = __ldg((const float4*)(rp + colB));  // cols 4p..4p+3

        float v0 = left ? 0.f : A.w;
        float v1 = B.x, v2 = B.y, v3 = B.z, v4 = B.w;
        if (top && r == 0) { v0 = 0.f; v1 = 0.f; v2 = 0.f; v3 = 0.f; v4 = 0.f; }

        float e0 = ex2f(c * v0), e1 = ex2f(c * v1), e2 = ex2f(c * v2);
        float e3 = ex2f(c * v3), e4 = ex2f(c * v4);

        // left window = cols {0,1,2}, right window = cols {2,3,4}; col 2 shared
        float ve2 = v2 * e2;
        float dl = e0 + e1 + e2;
        float dr = e2 + e3 + e4;
        float nl = fmaf(v0, e0, fmaf(v1, e1, ve2));
        float nr = fmaf(v3, e3, fmaf(v4, e4, ve2));

        // rows 0..2 -> out row 2q; rows 2..4 -> out row 2q+1 (row 2 shared)
        if (r <= 2) { den00 += dl; den01 += dr; num00 += nl; num01 += nr; }
        if (r >= 2) { den10 += dl; den11 += dr; num10 += nl; num11 += nr; }
    }

    float* op = out + (size_t)nc * PLANE_OUT + (size_t)(2u * q) * W_OUT + 2u * p;
    // Streaming stores: output is write-once; keep it from displacing input rows in L2.
    __stcs((float2*)op,           make_float2(num00 * frcp(den00), num01 * frcp(den01)));
    __stcs((float2*)(op + W_OUT), make_float2(num10 * frcp(den10), num11 * frcp(den11)));
}

extern "C" void kernel_launch(void* const* d_in, const int* in_sizes, int n_in,
                              void* d_out, int out_size) {
    const float* x         = (const float*)d_in[0];
    const float* raw_alpha = (const float*)d_in[1];
    float*       out       = (float*)d_out;

    const int block = 256;
    const int grid  = TOTAL_TILES / block;  // 18816, exact
    softpool_kernel<<<grid, block>>>(x, raw_alpha, out);
}